// round 10
// baseline (speedup 1.0000x reference)
#include <cuda_runtime.h>
#include <cuda_bf16.h>

#define N_POINTS    262144
#define NUM_CLASSES 20
#define K_NEIGHBORS 16
#define FULLMASK    0xffffffffu

// packed labels: 5 bits each, 6 per uint32
#define NWORDS      43691            // ceil(262144 / 6)
#define NWORDS_PAD  43692            // multiple of 4 for uint4 copies
#define SMEM_BYTES  (NWORDS_PAD * 4) // 174768 B

#define GRIDF       148              // <= SM count; every block resident (175KB smem => 1/SM)
#define TPBF        1024
#define N_TASKS     (N_POINTS * 4)   // (point, quarter) tasks, 4 neighbors each

// probs stored as 5 transposed float4 planes: plane j at [j*N + i]
__device__ float4 g_probs[5 * N_POINTS];
__device__ unsigned g_packed[NWORDS_PAD];
__device__ signed char g_lab8[N_POINTS];
__device__ double g_sum;
__device__ unsigned long long g_count;
__device__ unsigned int g_done;   // zero at start; last block resets
__device__ unsigned int g_bar;    // device-wide barrier; last block resets

// ---------------------------------------------------------------------------
// Index-dtype detection (values lie in [0,N); int32 read as int64 -> OOB).
// ---------------------------------------------------------------------------
__device__ __forceinline__ bool detect_is64(const void* __restrict__ ref_raw) {
    __shared__ int s_is64;
    if (threadIdx.x < 32) {
        const long long* p = (const long long*)ref_raw;
        long long a = p[threadIdx.x];
        long long b = p[threadIdx.x + 32];
        int bad = (a < 0 || a >= (long long)N_POINTS ||
                   b < 0 || b >= (long long)N_POINTS) ? 1 : 0;
        unsigned m = __ballot_sync(FULLMASK, bad);
        if (threadIdx.x == 0) s_is64 = (m == 0u);
    }
    __syncthreads();
    return s_is64 != 0;
}

// neighbor label extract from packed smem table: q = i/6, r = i%6
__device__ __forceinline__ int lab_extract(const unsigned* __restrict__ tab, int i) {
    unsigned q = __umulhi((unsigned)i, 715827883u);   // floor(i/6) exact for i<2^18
    unsigned r = (unsigned)i - q * 6u;
    return (int)((tab[q] >> (r * 5u)) & 31u);
}

// ---------------------------------------------------------------------------
// Phase-2 core: process one task's 4 neighbors given its preloaded indices.
// ---------------------------------------------------------------------------
__device__ __forceinline__ void process_task(const unsigned* __restrict__ s_lab,
                                             int i, const int* idxv,
                                             float& acc, int& cnt) {
    int myl = (int)__ldg(&g_lab8[i]);   // coalesced byte; siblings broadcast

    unsigned mask = 0;
#pragma unroll
    for (int k = 0; k < 4; k++) {
        int safe = max(idxv[k], 0);
        int nl = lab_extract(s_lab, safe);
        if (idxv[k] >= 0 && nl == myl && myl != 31) mask |= 1u << k;
    }

    if (mask) {
        float4 sp[5];
#pragma unroll
        for (int j = 0; j < 5; j++) sp[j] = g_probs[j * N_POINTS + i];
        const float* s = (const float*)sp;

        do {
            int k = __ffs(mask) - 1;
            mask &= mask - 1;
            int idx = idxv[k];
            float d = 0.f;
#pragma unroll
            for (int j = 0; j < 5; j++) {
                float4 qq = g_probs[j * N_POINTS + idx];
                float d0 = s[j * 4 + 0] - qq.x;
                float d1 = s[j * 4 + 1] - qq.y;
                float d2 = s[j * 4 + 2] - qq.z;
                float d3 = s[j * 4 + 3] - qq.w;
                d = fmaf(d0, d0, d); d = fmaf(d1, d1, d);
                d = fmaf(d2, d2, d); d = fmaf(d3, d3, d);
            }
            acc += d;
            cnt++;
        } while (mask);
    }
}

// ---------------------------------------------------------------------------
// Fused persistent kernel: phase 1 (softmax + label pack) -> device barrier ->
// smem table fill -> phase 2 (matched distances) -> reduce -> finalize.
// ---------------------------------------------------------------------------
__global__ void __launch_bounds__(TPBF, 1)
lac_fused(const float* __restrict__ logits,
          const void* __restrict__ labels_raw,
          const void* __restrict__ ref_raw,
          float* __restrict__ out) {
    extern __shared__ unsigned s_lab[];
    const bool is64 = detect_is64(ref_raw);
    const int tid = threadIdx.x;
    const int gtid = blockIdx.x * TPBF + tid;
    const int gstride = GRIDF * TPBF;   // 151552

    if (blockIdx.x == 0 && tid == 0) { g_sum = 0.0; g_count = 0ULL; }

    // ---- Phase 1a: pack labels 5-bit (6/word) + int8 copy ----
    for (int wi = gtid; wi < NWORDS_PAD; wi += gstride) {
        unsigned w = 0;
#pragma unroll
        for (int t = 0; t < 6; t++) {
            int p = wi * 6 + t;
            int lbl = 31;   // invalid sentinel
            if (p < N_POINTS) {
                long long v = is64 ? ((const long long*)labels_raw)[p]
                                   : (long long)((const int*)labels_raw)[p];
                lbl = (int)v & 31;   // -1 -> 31; 0..19 preserved
            }
            w |= (unsigned)lbl << (t * 5);
        }
        g_packed[wi] = w;
    }

    // ---- Phase 1b: int8 labels + softmax into transposed planes ----
    for (int i = gtid; i < N_POINTS; i += gstride) {
        long long v = is64 ? ((const long long*)labels_raw)[i]
                           : (long long)((const int*)labels_raw)[i];
        g_lab8[i] = (signed char)((int)v & 31);

        const float4* in = (const float4*)logits + (long long)i * 5;
        float4 vv[5];
#pragma unroll
        for (int j = 0; j < 5; j++) vv[j] = in[j];
        float* f = (float*)vv;

        float m = f[0];
#pragma unroll
        for (int j = 1; j < NUM_CLASSES; j++) m = fmaxf(m, f[j]);
        float s = 0.f;
#pragma unroll
        for (int j = 0; j < NUM_CLASSES; j++) { float e = __expf(f[j] - m); f[j] = e; s += e; }
        float inv = __frcp_rn(s);
#pragma unroll
        for (int j = 0; j < NUM_CLASSES; j++) f[j] *= inv;

#pragma unroll
        for (int j = 0; j < 5; j++) g_probs[j * N_POINTS + i] = vv[j];
    }

    // ---- Device-wide barrier (all GRIDF blocks resident by construction) ----
    __threadfence();              // publish phase-1 stores
    __syncthreads();
    if (tid == 0) {
        atomicAdd(&g_bar, 1u);
        while (*(volatile unsigned*)&g_bar < (unsigned)GRIDF) { }
    }
    __syncthreads();
    __threadfence();              // acquire phase-1 stores from other blocks

    // ---- Fill smem label table ----
    {
        const uint4* src = (const uint4*)g_packed;
        uint4* dst = (uint4*)s_lab;
        for (int t = tid; t < NWORDS_PAD / 4; t += TPBF)
            dst[t] = src[t];
    }
    __syncthreads();

    // ---- Phase 2: (point,quarter) tasks, distance-1 index prefetch ----
    float acc = 0.f;
    int   cnt = 0;

    if (!is64) {
        const int4* ref32 = (const int4*)ref_raw;   // task t -> ref32[t]
        int task = gtid;
        int4 buf = ref32[min(task, N_TASKS - 1)];
        while (task < N_TASKS) {
            int next = task + gstride;
            int4 nbuf = ref32[min(next, N_TASKS - 1)];   // prefetch (clamped)
            int idxv[4] = { buf.x, buf.y, buf.z, buf.w };
            process_task(s_lab, task >> 2, idxv, acc, cnt);
            buf = nbuf;
            task = next;
        }
    } else {
        const int4* ref64 = (const int4*)ref_raw;   // task t -> ref64[2t], ref64[2t+1]
        int task = gtid;
        int c = min(task, N_TASKS - 1);
        int4 b0 = ref64[2 * c], b1 = ref64[2 * c + 1];
        while (task < N_TASKS) {
            int next = task + gstride;
            int nc = min(next, N_TASKS - 1);
            int4 n0 = ref64[2 * nc], n1 = ref64[2 * nc + 1];   // prefetch
            int idxv[4] = { b0.x, b0.z, b1.x, b1.z };          // low words; -1 preserved
            process_task(s_lab, task >> 2, idxv, acc, cnt);
            b0 = n0; b1 = n1;
            task = next;
        }
    }

    // ---- Block reduction -> one atomic per block -> last-block finalize ----
#pragma unroll
    for (int o = 16; o > 0; o >>= 1) {
        acc += __shfl_down_sync(FULLMASK, acc, o);
        cnt += __shfl_down_sync(FULLMASK, cnt, o);
    }
    __shared__ float ssum[32];
    __shared__ int   scnt[32];
    int lane = tid & 31;
    int w    = tid >> 5;
    if (lane == 0) { ssum[w] = acc; scnt[w] = cnt; }
    __syncthreads();
    if (w == 0) {
        acc = ssum[lane];
        cnt = scnt[lane];
#pragma unroll
        for (int o = 16; o > 0; o >>= 1) {
            acc += __shfl_down_sync(FULLMASK, acc, o);
            cnt += __shfl_down_sync(FULLMASK, cnt, o);
        }
        if (lane == 0) {
            atomicAdd(&g_sum, (double)acc);
            atomicAdd(&g_count, (unsigned long long)cnt);
            __threadfence();
            unsigned int done = atomicAdd(&g_done, 1u);
            if (done == GRIDF - 1) {
                double sum = *(volatile double*)&g_sum;
                double c   = (double)*(volatile unsigned long long*)&g_count;
                if (c < 1.0) c = 1.0;
                out[0] = (float)(sum / c);
                g_done = 0;   // self-reset for next graph replay
                g_bar  = 0;   // barrier reset for next graph replay
            }
        }
    }
}

extern "C" void kernel_launch(void* const* d_in, const int* in_sizes, int n_in,
                              void* d_out, int out_size) {
    const float* seg_logits = (const float*)d_in[0];
    // d_in[1] = coord, unused
    const void* labels = d_in[2];
    const void* ref    = d_in[3];
    float* out = (float*)d_out;

    cudaFuncSetAttribute(lac_fused, cudaFuncAttributeMaxDynamicSharedMemorySize,
                         SMEM_BYTES);

    lac_fused<<<GRIDF, TPBF, SMEM_BYTES>>>(seg_logits, labels, ref, out);
}

// round 11
// speedup vs baseline: 1.0094x; 1.0094x over previous
#include <cuda_runtime.h>
#include <cuda_bf16.h>

#define N_POINTS    262144
#define NUM_CLASSES 20
#define K_NEIGHBORS 16
#define FULLMASK    0xffffffffu

// packed labels: 5 bits each, 6 per uint32
#define NWORDS      43691            // ceil(262144 / 6)
#define NWORDS_PAD  43692            // multiple of 4 for uint4 copies
#define SMEM_BYTES  (NWORDS_PAD * 4) // 174768 B

#define GRID2       152
#define TPB2        1024
#define N_TASKS     (N_POINTS * 4)   // (point, quarter) tasks, 4 neighbors each

// probs stored as 5 transposed float4 planes: plane j at [j*N + i]
__device__ float4 g_probs[5 * N_POINTS];
__device__ unsigned g_packed[NWORDS_PAD];
__device__ signed char g_lab8[N_POINTS];
__device__ double g_sum;
__device__ unsigned long long g_count;
__device__ unsigned int g_done;

// ---------------------------------------------------------------------------
// Index-dtype detection (values lie in [0,N); int32 read as int64 -> OOB).
// ---------------------------------------------------------------------------
__device__ __forceinline__ bool detect_is64(const void* __restrict__ ref_raw) {
    __shared__ int s_is64;
    if (threadIdx.x < 32) {
        const long long* p = (const long long*)ref_raw;
        long long a = p[threadIdx.x];
        long long b = p[threadIdx.x + 32];
        int bad = (a < 0 || a >= (long long)N_POINTS ||
                   b < 0 || b >= (long long)N_POINTS) ? 1 : 0;
        unsigned m = __ballot_sync(FULLMASK, bad);
        if (threadIdx.x == 0) s_is64 = (m == 0u);
    }
    __syncthreads();
    return s_is64 != 0;
}

// neighbor label extract from packed smem table: q = i/6, r = i%6
__device__ __forceinline__ int lab_extract(const unsigned* __restrict__ tab, int i) {
    unsigned q = __umulhi((unsigned)i, 715827883u);   // floor(i/6) exact for i<2^18
    unsigned r = (unsigned)i - q * 6u;
    return (int)((tab[q] >> (r * 5u)) & 31u);
}

// ---------------------------------------------------------------------------
// Pass 1: zero accumulators, labels -> int8 + packed 5-bit, softmax -> planes.
// ---------------------------------------------------------------------------
__global__ void lac_pass1(const float* __restrict__ logits,
                          const void* __restrict__ labels_raw,
                          const void* __restrict__ ref_raw) {
    const bool is64 = detect_is64(ref_raw);
    int i = blockIdx.x * blockDim.x + threadIdx.x;
    if (blockIdx.x == 0 && threadIdx.x == 0) { g_sum = 0.0; g_count = 0ULL; }

    if (i < NWORDS_PAD) {
        unsigned w = 0;
#pragma unroll
        for (int t = 0; t < 6; t++) {
            int p = i * 6 + t;
            int lbl = 31;   // invalid sentinel
            if (p < N_POINTS) {
                long long v = is64 ? ((const long long*)labels_raw)[p]
                                   : (long long)((const int*)labels_raw)[p];
                lbl = (int)v & 31;   // -1 -> 31 (invalid); 0..19 preserved
            }
            w |= (unsigned)lbl << (t * 5);
        }
        g_packed[i] = w;
    }

    if (i >= N_POINTS) return;

    {   // int8 label for the coalesced self-label read in pass 2 (31 = invalid)
        long long v = is64 ? ((const long long*)labels_raw)[i]
                           : (long long)((const int*)labels_raw)[i];
        g_lab8[i] = (signed char)((int)v & 31);
    }

    const float4* in = (const float4*)logits + (long long)i * 5;
    float4 v[5];
#pragma unroll
    for (int j = 0; j < 5; j++) v[j] = in[j];
    float* f = (float*)v;

    float m = f[0];
#pragma unroll
    for (int j = 1; j < NUM_CLASSES; j++) m = fmaxf(m, f[j]);
    float s = 0.f;
#pragma unroll
    for (int j = 0; j < NUM_CLASSES; j++) { float e = __expf(f[j] - m); f[j] = e; s += e; }
    float inv = __frcp_rn(s);
#pragma unroll
    for (int j = 0; j < NUM_CLASSES; j++) f[j] *= inv;

#pragma unroll
    for (int j = 0; j < 5; j++) g_probs[j * N_POINTS + i] = v[j];   // transposed planes
}

// ---------------------------------------------------------------------------
// Pass 2 core: hoisted self loads (coalesced, issued before LDS mask chain),
// L2-only neighbor gathers.
// ---------------------------------------------------------------------------
__device__ __forceinline__ void process_task(const unsigned* __restrict__ s_lab,
                                             int i, const int* idxv,
                                             float& acc, int& cnt) {
    // self label + self probs issued FIRST: coalesced (siblings share rows),
    // independent of the LDS label lookups that follow.
    int myl = (int)__ldg(&g_lab8[i]);
    float4 sp[5];
#pragma unroll
    for (int j = 0; j < 5; j++) sp[j] = g_probs[j * N_POINTS + i];
    const float* s = (const float*)sp;

    unsigned mask = 0;
#pragma unroll
    for (int k = 0; k < 4; k++) {
        int safe = max(idxv[k], 0);
        int nl = lab_extract(s_lab, safe);
        if (idxv[k] >= 0 && nl == myl) mask |= 1u << k;
    }
    if (myl == 31) mask = 0;   // single fold of center-valid

    while (mask) {
        int k = __ffs(mask) - 1;
        mask &= mask - 1;
        int idx = idxv[k];
        float d = 0.f;
#pragma unroll
        for (int j = 0; j < 3; j++) { /* placeholder to keep unroll shape */ }
#pragma unroll
        for (int j = 0; j < 5; j++) {
            float4 qq = __ldcg(&g_probs[j * N_POINTS + idx]);   // L2-only gather
            float d0 = s[j * 4 + 0] - qq.x;
            float d1 = s[j * 4 + 1] - qq.y;
            float d2 = s[j * 4 + 2] - qq.z;
            float d3 = s[j * 4 + 3] - qq.w;
            d = fmaf(d0, d0, d); d = fmaf(d1, d1, d);
            d = fmaf(d2, d2, d); d = fmaf(d3, d3, d);
        }
        acc += d;
        cnt++;
    }
}

// ---------------------------------------------------------------------------
// Pass 2: persistent blocks; smem label table; (point,quarter) tasks with
// distance-1 register prefetch of the next index vector; reduce; finalize.
// ---------------------------------------------------------------------------
__global__ void __launch_bounds__(TPB2, 1)
lac_pass2(const void* __restrict__ ref_raw, float* __restrict__ out) {
    extern __shared__ unsigned s_lab[];
    const bool is64 = detect_is64(ref_raw);

    {
        const uint4* src = (const uint4*)g_packed;
        uint4* dst = (uint4*)s_lab;
        for (int t = threadIdx.x; t < NWORDS_PAD / 4; t += blockDim.x)
            dst[t] = src[t];
    }
    __syncthreads();

    float acc = 0.f;
    int   cnt = 0;

    const int stride = GRID2 * TPB2;
    const int t0 = blockIdx.x * TPB2 + threadIdx.x;

    if (!is64) {
        // ---- int32 indices: one int4 per task, prefetch distance 1 ----
        const int4* ref32 = (const int4*)ref_raw;   // task t -> ref32[t]
        int task = t0;
        int4 buf = ref32[min(task, N_TASKS - 1)];
        while (task < N_TASKS) {
            int next = task + stride;
            int4 nbuf = ref32[min(next, N_TASKS - 1)];   // prefetch (clamped)
            int idxv[4] = { buf.x, buf.y, buf.z, buf.w };
            process_task(s_lab, task >> 2, idxv, acc, cnt);
            buf = nbuf;
            task = next;
        }
    } else {
        // ---- int64 indices: two int4 per task, prefetch distance 1 ----
        const int4* ref64 = (const int4*)ref_raw;   // task t -> ref64[2t], ref64[2t+1]
        int task = t0;
        int c = min(task, N_TASKS - 1);
        int4 b0 = ref64[2 * c], b1 = ref64[2 * c + 1];
        while (task < N_TASKS) {
            int next = task + stride;
            int nc = min(next, N_TASKS - 1);
            int4 n0 = ref64[2 * nc], n1 = ref64[2 * nc + 1];   // prefetch
            int idxv[4] = { b0.x, b0.z, b1.x, b1.z };          // low words; -1 preserved
            process_task(s_lab, task >> 2, idxv, acc, cnt);
            b0 = n0; b1 = n1;
            task = next;
        }
    }

    // block reduction (32 warps) -> one atomic per block -> last-block finalize
#pragma unroll
    for (int o = 16; o > 0; o >>= 1) {
        acc += __shfl_down_sync(FULLMASK, acc, o);
        cnt += __shfl_down_sync(FULLMASK, cnt, o);
    }
    __shared__ float ssum[32];
    __shared__ int   scnt[32];
    int lane = threadIdx.x & 31;
    int w    = threadIdx.x >> 5;
    if (lane == 0) { ssum[w] = acc; scnt[w] = cnt; }
    __syncthreads();
    if (w == 0) {
        acc = ssum[lane];
        cnt = scnt[lane];
#pragma unroll
        for (int o = 16; o > 0; o >>= 1) {
            acc += __shfl_down_sync(FULLMASK, acc, o);
            cnt += __shfl_down_sync(FULLMASK, cnt, o);
        }
        if (lane == 0) {
            atomicAdd(&g_sum, (double)acc);
            atomicAdd(&g_count, (unsigned long long)cnt);
            __threadfence();
            unsigned int done = atomicAdd(&g_done, 1u);
            if (done == gridDim.x - 1) {
                double sum = *(volatile double*)&g_sum;
                double c   = (double)*(volatile unsigned long long*)&g_count;
                if (c < 1.0) c = 1.0;
                out[0] = (float)(sum / c);
                g_done = 0;   // self-reset for next graph replay
            }
        }
    }
}

extern "C" void kernel_launch(void* const* d_in, const int* in_sizes, int n_in,
                              void* d_out, int out_size) {
    const float* seg_logits = (const float*)d_in[0];
    // d_in[1] = coord, unused
    const void* labels = d_in[2];
    const void* ref    = d_in[3];
    float* out = (float*)d_out;

    cudaFuncSetAttribute(lac_pass2, cudaFuncAttributeMaxDynamicSharedMemorySize,
                         SMEM_BYTES);

    const int TPB1 = 256;
    const int blocks1 = (N_POINTS + TPB1 - 1) / TPB1;   // 1024

    lac_pass1<<<blocks1, TPB1>>>(seg_logits, labels, ref);
    lac_pass2<<<GRID2, TPB2, SMEM_BYTES>>>(ref, out);
}

// round 12
// speedup vs baseline: 1.1889x; 1.1778x over previous
#include <cuda_runtime.h>
#include <cuda_bf16.h>
#include <cuda_fp16.h>

#define N_POINTS    262144
#define NUM_CLASSES 20
#define K_NEIGHBORS 16
#define FULLMASK    0xffffffffu

// packed labels: 5 bits each, 6 per uint32
#define NWORDS      43691            // ceil(262144 / 6)
#define NWORDS_PAD  43692            // multiple of 4 for uint4 copies
#define SMEM_BYTES  (NWORDS_PAD * 4) // 174768 B

#define GRID2       152
#define TPB2        1024
#define N_TASKS     (N_POINTS * 4)   // (point, quarter) tasks, 4 neighbors each

// probs as fp16: 3 transposed uint4 planes (8 halves = 8 classes per plane; 20..23 zero)
__device__ uint4 g_probsh[3 * N_POINTS];
__device__ unsigned g_packed[NWORDS_PAD];
__device__ signed char g_lab8[N_POINTS];
__device__ double g_sum;
__device__ unsigned long long g_count;
__device__ unsigned int g_done;

// ---------------------------------------------------------------------------
// Index-dtype detection (values lie in [0,N); int32 read as int64 -> OOB).
// ---------------------------------------------------------------------------
__device__ __forceinline__ bool detect_is64(const void* __restrict__ ref_raw) {
    __shared__ int s_is64;
    if (threadIdx.x < 32) {
        const long long* p = (const long long*)ref_raw;
        long long a = p[threadIdx.x];
        long long b = p[threadIdx.x + 32];
        int bad = (a < 0 || a >= (long long)N_POINTS ||
                   b < 0 || b >= (long long)N_POINTS) ? 1 : 0;
        unsigned m = __ballot_sync(FULLMASK, bad);
        if (threadIdx.x == 0) s_is64 = (m == 0u);
    }
    __syncthreads();
    return s_is64 != 0;
}

// neighbor label extract from packed smem table: q = i/6, r = i%6
__device__ __forceinline__ int lab_extract(const unsigned* __restrict__ tab, int i) {
    unsigned q = __umulhi((unsigned)i, 715827883u);   // floor(i/6) exact for i<2^18
    unsigned r = (unsigned)i - q * 6u;
    return (int)((tab[q] >> (r * 5u)) & 31u);
}

// subtract in half2, convert the DIFF once, square-accumulate in fp32
__device__ __forceinline__ float acc2(unsigned ua, unsigned ub, float d) {
    __half2 df = __hsub2(*(const __half2*)&ua, *(const __half2*)&ub);
    float2 f = __half22float2(df);
    d = fmaf(f.x, f.x, d);
    return fmaf(f.y, f.y, d);
}

// ---------------------------------------------------------------------------
// Pass 1: zero accumulators, labels -> int8 + packed 5-bit, softmax -> fp16 planes.
// ---------------------------------------------------------------------------
__global__ void lac_pass1(const float* __restrict__ logits,
                          const void* __restrict__ labels_raw,
                          const void* __restrict__ ref_raw) {
    const bool is64 = detect_is64(ref_raw);
    int i = blockIdx.x * blockDim.x + threadIdx.x;
    if (blockIdx.x == 0 && threadIdx.x == 0) { g_sum = 0.0; g_count = 0ULL; }

    if (i < NWORDS_PAD) {
        unsigned w = 0;
#pragma unroll
        for (int t = 0; t < 6; t++) {
            int p = i * 6 + t;
            int lbl = 31;   // invalid sentinel
            if (p < N_POINTS) {
                long long v = is64 ? ((const long long*)labels_raw)[p]
                                   : (long long)((const int*)labels_raw)[p];
                lbl = (int)v & 31;   // -1 -> 31 (invalid); 0..19 preserved
            }
            w |= (unsigned)lbl << (t * 5);
        }
        g_packed[i] = w;
    }

    if (i >= N_POINTS) return;

    {   // int8 label for the coalesced self-label read in pass 2 (31 = invalid)
        long long v = is64 ? ((const long long*)labels_raw)[i]
                           : (long long)((const int*)labels_raw)[i];
        g_lab8[i] = (signed char)((int)v & 31);
    }

    const float4* in = (const float4*)logits + (long long)i * 5;
    float4 v[5];
#pragma unroll
    for (int j = 0; j < 5; j++) v[j] = in[j];
    float* f = (float*)v;

    float m = f[0];
#pragma unroll
    for (int j = 1; j < NUM_CLASSES; j++) m = fmaxf(m, f[j]);
    float s = 0.f;
#pragma unroll
    for (int j = 0; j < NUM_CLASSES; j++) { float e = __expf(f[j] - m); f[j] = e; s += e; }
    float inv = __frcp_rn(s);
#pragma unroll
    for (int j = 0; j < NUM_CLASSES; j++) f[j] *= inv;

    // pack to 10 half2 + 2 zero half2, store as 3 uint4 planes (transposed)
    unsigned h[12];
#pragma unroll
    for (int c = 0; c < 10; c++) {
        __half2 hh = __floats2half2_rn(f[2 * c], f[2 * c + 1]);
        h[c] = *(unsigned*)&hh;
    }
    h[10] = 0u; h[11] = 0u;
#pragma unroll
    for (int j = 0; j < 3; j++) {
        uint4 P;
        P.x = h[j * 4 + 0]; P.y = h[j * 4 + 1];
        P.z = h[j * 4 + 2]; P.w = h[j * 4 + 3];
        g_probsh[j * N_POINTS + i] = P;
    }
}

// ---------------------------------------------------------------------------
// Pass 2 core (R9 structure): byte self-label, LDS mask, conditional self
// loads, ffs match loop; fp16 planes with hsub2 distance body.
// ---------------------------------------------------------------------------
__device__ __forceinline__ void process_task(const unsigned* __restrict__ s_lab,
                                             int i, const int* idxv,
                                             float& acc, int& cnt) {
    int myl = (int)__ldg(&g_lab8[i]);   // coalesced byte; siblings broadcast

    unsigned mask = 0;
#pragma unroll
    for (int k = 0; k < 4; k++) {
        int safe = max(idxv[k], 0);
        int nl = lab_extract(s_lab, safe);
        if (idxv[k] >= 0 && nl == myl && myl != 31) mask |= 1u << k;
    }

    if (mask) {
        uint4 sp[3];
#pragma unroll
        for (int j = 0; j < 3; j++) sp[j] = g_probsh[j * N_POINTS + i];

        do {
            int k = __ffs(mask) - 1;
            mask &= mask - 1;
            int idx = idxv[k];
            float d = 0.f;
#pragma unroll
            for (int j = 0; j < 3; j++) {
                uint4 qq = g_probsh[j * N_POINTS + idx];
                d = acc2(sp[j].x, qq.x, d);
                d = acc2(sp[j].y, qq.y, d);
                d = acc2(sp[j].z, qq.z, d);
                d = acc2(sp[j].w, qq.w, d);
            }
            acc += d;
            cnt++;
        } while (mask);
    }
}

// ---------------------------------------------------------------------------
// Pass 2: persistent blocks; smem label table; (point,quarter) tasks with
// distance-1 register prefetch of the next index vector; reduce; finalize.
// ---------------------------------------------------------------------------
__global__ void __launch_bounds__(TPB2, 1)
lac_pass2(const void* __restrict__ ref_raw, float* __restrict__ out) {
    extern __shared__ unsigned s_lab[];
    const bool is64 = detect_is64(ref_raw);

    {
        const uint4* src = (const uint4*)g_packed;
        uint4* dst = (uint4*)s_lab;
        for (int t = threadIdx.x; t < NWORDS_PAD / 4; t += blockDim.x)
            dst[t] = src[t];
    }
    __syncthreads();

    float acc = 0.f;
    int   cnt = 0;

    const int stride = GRID2 * TPB2;
    const int t0 = blockIdx.x * TPB2 + threadIdx.x;

    if (!is64) {
        // ---- int32 indices: one int4 per task, prefetch distance 1 ----
        const int4* ref32 = (const int4*)ref_raw;   // task t -> ref32[t]
        int task = t0;
        int4 buf = ref32[min(task, N_TASKS - 1)];
        while (task < N_TASKS) {
            int next = task + stride;
            int4 nbuf = ref32[min(next, N_TASKS - 1)];   // prefetch (clamped)
            int idxv[4] = { buf.x, buf.y, buf.z, buf.w };
            process_task(s_lab, task >> 2, idxv, acc, cnt);
            buf = nbuf;
            task = next;
        }
    } else {
        // ---- int64 indices: two int4 per task, prefetch distance 1 ----
        const int4* ref64 = (const int4*)ref_raw;   // task t -> ref64[2t], ref64[2t+1]
        int task = t0;
        int c = min(task, N_TASKS - 1);
        int4 b0 = ref64[2 * c], b1 = ref64[2 * c + 1];
        while (task < N_TASKS) {
            int next = task + stride;
            int nc = min(next, N_TASKS - 1);
            int4 n0 = ref64[2 * nc], n1 = ref64[2 * nc + 1];   // prefetch
            int idxv[4] = { b0.x, b0.z, b1.x, b1.z };          // low words; -1 preserved
            process_task(s_lab, task >> 2, idxv, acc, cnt);
            b0 = n0; b1 = n1;
            task = next;
        }
    }

    // block reduction (32 warps) -> one atomic per block -> last-block finalize
#pragma unroll
    for (int o = 16; o > 0; o >>= 1) {
        acc += __shfl_down_sync(FULLMASK, acc, o);
        cnt += __shfl_down_sync(FULLMASK, cnt, o);
    }
    __shared__ float ssum[32];
    __shared__ int   scnt[32];
    int lane = threadIdx.x & 31;
    int w    = threadIdx.x >> 5;
    if (lane == 0) { ssum[w] = acc; scnt[w] = cnt; }
    __syncthreads();
    if (w == 0) {
        acc = ssum[lane];
        cnt = scnt[lane];
#pragma unroll
        for (int o = 16; o > 0; o >>= 1) {
            acc += __shfl_down_sync(FULLMASK, acc, o);
            cnt += __shfl_down_sync(FULLMASK, cnt, o);
        }
        if (lane == 0) {
            atomicAdd(&g_sum, (double)acc);
            atomicAdd(&g_count, (unsigned long long)cnt);
            __threadfence();
            unsigned int done = atomicAdd(&g_done, 1u);
            if (done == gridDim.x - 1) {
                double sum = *(volatile double*)&g_sum;
                double c   = (double)*(volatile unsigned long long*)&g_count;
                if (c < 1.0) c = 1.0;
                out[0] = (float)(sum / c);
                g_done = 0;   // self-reset for next graph replay
            }
        }
    }
}

extern "C" void kernel_launch(void* const* d_in, const int* in_sizes, int n_in,
                              void* d_out, int out_size) {
    const float* seg_logits = (const float*)d_in[0];
    // d_in[1] = coord, unused
    const void* labels = d_in[2];
    const void* ref    = d_in[3];
    float* out = (float*)d_out;

    cudaFuncSetAttribute(lac_pass2, cudaFuncAttributeMaxDynamicSharedMemorySize,
                         SMEM_BYTES);

    const int TPB1 = 512;
    const int blocks1 = (N_POINTS + TPB1 - 1) / TPB1;   // 512

    lac_pass1<<<blocks1, TPB1>>>(seg_logits, labels, ref);
    lac_pass2<<<GRID2, TPB2, SMEM_BYTES>>>(ref, out);
}